// round 1
// baseline (speedup 1.0000x reference)
#include <cuda_runtime.h>
#include <math.h>

// ---------------- problem constants ----------------
constexpr int cB = 32, cC = 3, cIMG = 224, cPS = 16, cG = 14, cNP = 196;
constexpr int cD = 768, cH = 12, cHD = 64, cL = 12, cMLP = 3072;
constexpr int cPOOL = 10, cSEL = 5, cPLEN = 5, cNCLS = 100;
constexpr int cS1 = 197, cS2 = 222;

// ---------------- scratch (device globals; no allocation allowed) ----------------
__device__ float g_x0 [cB*cS1*cD];        // embedded input (kept for pass 2)
__device__ float g_x  [cB*cS2*cD];        // residual stream
__device__ float g_h  [cB*cS2*cD];        // LN output
__device__ float g_qkv[cB*cS2*3*cD];
__device__ float g_att[cB*cH*cS2*cS2];
__device__ float g_ao [cB*cS2*cD];
__device__ float g_mlp[cB*cS2*cMLP];
__device__ float g_patch[cB*cNP*cD];
__device__ float g_cls[cB*cD];
__device__ float g_fro[cPOOL];
__device__ float g_routc[cPOOL];
__device__ float g_score[cB*cPOOL];
__device__ int   g_topk[cB*cSEL];
__device__ float g_feat[cB*cD];

// ---------------- reductions (blockDim == 256) ----------------
__device__ __forceinline__ float block_sum(float v, float* red) {
    int t = threadIdx.x;
    #pragma unroll
    for (int o = 16; o > 0; o >>= 1) v += __shfl_xor_sync(0xffffffffu, v, o);
    if ((t & 31) == 0) red[t >> 5] = v;
    __syncthreads();
    if (t == 0) {
        float s = 0.f;
        #pragma unroll
        for (int i = 0; i < 8; i++) s += red[i];
        red[0] = s;
    }
    __syncthreads();
    float r = red[0];
    __syncthreads();
    return r;
}

__device__ __forceinline__ float block_max(float v, float* red) {
    int t = threadIdx.x;
    #pragma unroll
    for (int o = 16; o > 0; o >>= 1) v = fmaxf(v, __shfl_xor_sync(0xffffffffu, v, o));
    if ((t & 31) == 0) red[t >> 5] = v;
    __syncthreads();
    if (t == 0) {
        float m = red[0];
        #pragma unroll
        for (int i = 1; i < 8; i++) m = fmaxf(m, red[i]);
        red[0] = m;
    }
    __syncthreads();
    float r = red[0];
    __syncthreads();
    return r;
}

// ---------------- generic batched GEMM ----------------
// C = act( alpha * A@B (+bias) (+Res) ), row-major, optional B^T.
// Batch index z decomposed as (bb, hh) = (z / HB, z % HB) with separate strides,
// so attention (batch = B*H with non-uniform strides) reuses the same kernel.
__global__ __launch_bounds__(256) void gemm_kernel(
    const float* __restrict__ A, const float* __restrict__ Bm, float* __restrict__ C,
    int M, int N, int K, int lda, int ldb, int ldc,
    int HB,
    long long sAb, long long sAh, long long sBb, long long sBh,
    long long sCb, long long sCh,
    const float* __restrict__ bias, const float* __restrict__ Res,
    float alpha, int transB, int act)
{
    __shared__ float As[16][68];
    __shared__ float Bs[16][68];
    int t  = threadIdx.x;
    int bz = blockIdx.z;
    int bb = bz / HB, hh = bz - bb * HB;
    const float* Ab = A  + bb * sAb + hh * sAh;
    const float* Bb = Bm + bb * sBb + hh * sBh;
    float*       Cb = C  + bb * sCb + hh * sCh;
    const float* Rb = Res ? Res + bb * sCb + hh * sCh : (const float*)0;
    int row0 = blockIdx.y * 64, col0 = blockIdx.x * 64;
    int tx = t & 15, ty = t >> 4;
    float acc[4][4];
    #pragma unroll
    for (int i = 0; i < 4; i++)
        #pragma unroll
        for (int j = 0; j < 4; j++) acc[i][j] = 0.f;

    for (int k0 = 0; k0 < K; k0 += 16) {
        #pragma unroll
        for (int s = 0; s < 4; s++) {
            int e = t * 4 + s;
            int m = e >> 4, kk = e & 15;
            int gr = row0 + m, gk = k0 + kk;
            As[kk][m] = (gr < M && gk < K) ? Ab[(long long)gr * lda + gk] : 0.f;
        }
        if (transB) {
            #pragma unroll
            for (int s = 0; s < 4; s++) {
                int e = t * 4 + s;
                int n = e >> 4, kk = e & 15;
                int gn = col0 + n, gk = k0 + kk;
                Bs[kk][n] = (gn < N && gk < K) ? Bb[(long long)gn * ldb + gk] : 0.f;
            }
        } else {
            #pragma unroll
            for (int s = 0; s < 4; s++) {
                int e = t + 256 * s;
                int kk = e >> 6, n = e & 63;
                int gn = col0 + n, gk = k0 + kk;
                Bs[kk][n] = (gn < N && gk < K) ? Bb[(long long)gk * ldb + gn] : 0.f;
            }
        }
        __syncthreads();
        #pragma unroll
        for (int kk = 0; kk < 16; kk++) {
            float4 a4 = *(const float4*)&As[kk][ty * 4];
            float4 b4 = *(const float4*)&Bs[kk][tx * 4];
            float ar[4] = {a4.x, a4.y, a4.z, a4.w};
            float br[4] = {b4.x, b4.y, b4.z, b4.w};
            #pragma unroll
            for (int i = 0; i < 4; i++)
                #pragma unroll
                for (int j = 0; j < 4; j++)
                    acc[i][j] = fmaf(ar[i], br[j], acc[i][j]);
        }
        __syncthreads();
    }

    #pragma unroll
    for (int i = 0; i < 4; i++) {
        int gr = row0 + ty * 4 + i;
        if (gr >= M) continue;
        #pragma unroll
        for (int j = 0; j < 4; j++) {
            int gc = col0 + tx * 4 + j;
            if (gc >= N) continue;
            float v = alpha * acc[i][j];
            if (bias) v += bias[gc];
            if (Rb)   v += Rb[(long long)gr * ldc + gc];
            if (act)  v = 0.5f * v * (1.f + erff(v * 0.70710678118654752f));  // exact GELU
            Cb[(long long)gr * ldc + gc] = v;
        }
    }
}

// ---------------- LayerNorm (cols == 768, blockDim == 256) ----------------
__global__ __launch_bounds__(256) void ln_kernel(
    const float* __restrict__ X, float* __restrict__ Y,
    long long istride, long long ostride,
    const float* __restrict__ w, const float* __restrict__ b)
{
    __shared__ float red[8];
    long long r = blockIdx.x;
    const float* x = X + r * istride;
    float*       y = Y + r * ostride;
    int t = threadIdx.x;
    float v[3];
    #pragma unroll
    for (int i = 0; i < 3; i++) v[i] = x[t + 256 * i];
    float mean = block_sum(v[0] + v[1] + v[2], red) * (1.f / 768.f);
    float d0 = v[0] - mean, d1 = v[1] - mean, d2 = v[2] - mean;
    float var = block_sum(d0*d0 + d1*d1 + d2*d2, red) * (1.f / 768.f);
    float rstd = rsqrtf(var + 1e-6f);
    #pragma unroll
    for (int i = 0; i < 3; i++) {
        int c = t + 256 * i;
        y[c] = (v[i] - mean) * rstd * w[c] + b[c];
    }
}

// ---------------- softmax over rows of length n (n <= 256) ----------------
__global__ __launch_bounds__(256) void softmax_kernel(float* __restrict__ X, int n)
{
    __shared__ float red[8];
    long long r = blockIdx.x;
    float* x = X + r * (long long)n;
    int t = threadIdx.x;
    float v = (t < n) ? x[t] : -3.4e38f;
    float mx = block_max(v, red);
    float e = (t < n) ? expf(v - mx) : 0.f;
    float s = block_sum(e, red);
    if (t < n) x[t] = e / s;
}

// ---------------- patchify ----------------
__global__ void patchify_kernel(const float* __restrict__ in)
{
    int total = cB * cNP * cD;
    for (int idx = blockIdx.x * blockDim.x + threadIdx.x; idx < total;
         idx += gridDim.x * blockDim.x) {
        int d  = idx % cD;
        int rp = idx / cD;
        int p  = rp % cNP;
        int b  = rp / cNP;
        int c  = d >> 8;
        int ph = (d >> 4) & 15;
        int pw = d & 15;
        int gy = p / cG, gx = p % cG;
        g_patch[idx] = in[((long long)(b * cC + c) * cIMG + gy * cPS + ph) * cIMG
                          + gx * cPS + pw];
    }
}

// ---------------- cls + pos embed (reads patch-embed output from g_ao) ----------------
__global__ void embed_kernel(const float* __restrict__ cls, const float* __restrict__ pos)
{
    int total = cB * cS1 * cD;
    for (int idx = blockIdx.x * blockDim.x + threadIdx.x; idx < total;
         idx += gridDim.x * blockDim.x) {
        int d  = idx % cD;
        int rs = idx / cD;
        int s  = rs % cS1;
        int b  = rs / cS1;
        float v = (s == 0) ? cls[d] : g_ao[((long long)b * cNP + (s - 1)) * cD + d];
        g_x0[idx] = v + pos[s * cD + d];
    }
}

__global__ void copy_x0_kernel()
{
    int total = cB * cS1 * cD;
    for (int idx = blockIdx.x * blockDim.x + threadIdx.x; idx < total;
         idx += gridDim.x * blockDim.x)
        g_x[idx] = g_x0[idx];
}

// ---------------- routing ----------------
__global__ __launch_bounds__(256) void fro_kernel(const float* __restrict__ var)
{
    __shared__ float red[8];
    int p = blockIdx.x;
    const float* vp = var + (long long)p * cD * cD;
    float s = 0.f;
    for (int i = threadIdx.x; i < cD * cD; i += 256) { float v = vp[i]; s += v * v; }
    s = block_sum(s, red);
    if (threadIdx.x == 0) g_fro[p] = s;
}

__global__ void routc_kernel(const float* __restrict__ freq)
{
    if (threadIdx.x == 0 && blockIdx.x == 0) {
        float mx = freq[0];
        for (int p = 1; p < cPOOL; p++) mx = fmaxf(mx, freq[p]);
        float w[cPOOL]; float nsq = 0.f;
        for (int p = 0; p < cPOOL; p++) { w[p] = mx - freq[p]; nsq += w[p] * w[p]; }
        float nrm = fmaxf(sqrtf(nsq), 1e-12f);
        for (int p = 0; p < cPOOL; p++) {
            float wn = w[p] / nrm;
            // lognorm = 0.5*log(||var||_F) = 0.25*log(sum_sq)
            g_routc[p] = 0.25f * logf(g_fro[p]) + logf(fmaxf(wn, 1e-30f));
        }
    }
}

__global__ __launch_bounds__(256) void score_kernel(const float* __restrict__ keypool,
                                                    const float* __restrict__ ivar)
{
    __shared__ float diff[cD];
    __shared__ float red[8];
    int p = blockIdx.x, b = blockIdx.y;
    for (int d = threadIdx.x; d < cD; d += 256)
        diff[d] = g_cls[b * cD + d] - keypool[p * cD + d];
    __syncthreads();
    const float* iv = ivar + (long long)p * cD * cD;
    float acc = 0.f;
    for (int idx = threadIdx.x; idx < cD * cD; idx += 256) {
        int d = idx / cD, e = idx - d * cD;
        acc += diff[d] * iv[idx] * diff[e];
    }
    float q = block_sum(acc, red);
    if (threadIdx.x == 0) g_score[b * cPOOL + p] = -0.5f * q + g_routc[p];
}

__global__ void topk_kernel()
{
    int b = threadIdx.x;
    if (b < cB) {
        float s[cPOOL]; bool used[cPOOL];
        for (int p = 0; p < cPOOL; p++) { s[p] = g_score[b * cPOOL + p]; used[p] = false; }
        for (int k = 0; k < cSEL; k++) {
            int best = 0; float bv = 3.4e38f; bool have = false;
            for (int p = 0; p < cPOOL; p++)
                if (!used[p] && (!have || s[p] < bv)) { bv = s[p]; best = p; have = true; }
            used[best] = true;
            g_topk[b * cSEL + k] = best;   // ascending score order (matches top_k(-score))
        }
    }
}

__global__ void buildsx_kernel(const float* __restrict__ prompts, const float* __restrict__ pos)
{
    int total = cB * cS2 * cD;
    for (int idx = blockIdx.x * blockDim.x + threadIdx.x; idx < total;
         idx += gridDim.x * blockDim.x) {
        int d  = idx % cD;
        int rs = idx / cD;
        int s  = rs % cS2;
        int b  = rs / cS2;
        float v;
        if (s == 0) {
            v = g_x0[(long long)b * cS1 * cD + d];
        } else if (s <= cSEL * cPLEN) {
            int k = (s - 1) / cPLEN, j = (s - 1) % cPLEN;
            int pr = g_topk[b * cSEL + k];
            v = prompts[((long long)pr * cPLEN + j) * cD + d] + pos[d];
        } else {
            v = g_x0[((long long)b * cS1 + (s - cSEL * cPLEN)) * cD + d];
        }
        g_x[idx] = v;
    }
}

__global__ __launch_bounds__(256) void featmean_kernel()
{
    int b = blockIdx.x;
    for (int d = threadIdx.x; d < cD; d += 256) {
        float s = 0.f;
        for (int t2 = 1; t2 <= cSEL * cPLEN; t2++)
            s += g_h[((long long)b * cS2 + t2) * cD + d];
        g_feat[b * cD + d] = s * (1.f / 25.f);
    }
}

// ---------------- host orchestration ----------------
static void launch_gemm(const float* A, const float* Bm, float* C,
                        int M, int N, int K, int lda, int ldb, int ldc,
                        int nb, int HB,
                        long long sAb, long long sAh, long long sBb, long long sBh,
                        long long sCb, long long sCh,
                        const float* bias, const float* Res,
                        float alpha, int transB, int act)
{
    dim3 grid((N + 63) / 64, (M + 63) / 64, nb);
    gemm_kernel<<<grid, 256>>>(A, Bm, C, M, N, K, lda, ldb, ldc, HB,
                               sAb, sAh, sBb, sBh, sCb, sCh, bias, Res,
                               alpha, transB, act);
}

struct Weights {
    const float *ln1_w, *ln1_b, *qkv_w, *qkv_b, *proj_w, *proj_b;
    const float *ln2_w, *ln2_b, *fc1_w, *fc1_b, *fc2_w, *fc2_b;
};

static void vit_layer(int S, int l, float* x, float* h, float* qkv, float* att,
                      float* ao, float* mlp, const Weights& W)
{
    int MS = cB * S;
    // LN1
    ln_kernel<<<MS, 256>>>(x, h, cD, cD, W.ln1_w + l * cD, W.ln1_b + l * cD);
    // qkv
    launch_gemm(h, W.qkv_w + (long long)l * cD * 3 * cD, qkv,
                MS, 3 * cD, cD, cD, 3 * cD, 3 * cD,
                1, 1, 0, 0, 0, 0, 0, 0,
                W.qkv_b + (long long)l * 3 * cD, nullptr, 1.f, 0, 0);
    // scores = Q @ K^T * HD^-0.5   (batch = B*H)
    launch_gemm(qkv, qkv + cD, att,
                S, S, cHD, 3 * cD, 3 * cD, S,
                cB * cH, cH,
                (long long)S * 3 * cD, cHD,
                (long long)S * 3 * cD, cHD,
                (long long)cH * S * S, (long long)S * S,
                nullptr, nullptr, 0.125f, 1, 0);
    softmax_kernel<<<cB * cH * S, 256>>>(att, S);
    // out = P @ V, written as [B, S, H*HD]
    launch_gemm(att, qkv + 2 * cD, ao,
                S, cHD, S, S, 3 * cD, cD,
                cB * cH, cH,
                (long long)cH * S * S, (long long)S * S,
                (long long)S * 3 * cD, cHD,
                (long long)S * cD, cHD,
                nullptr, nullptr, 1.f, 0, 0);
    // proj + residual
    launch_gemm(ao, W.proj_w + (long long)l * cD * cD, x,
                MS, cD, cD, cD, cD, cD,
                1, 1, 0, 0, 0, 0, 0, 0,
                W.proj_b + l * cD, x, 1.f, 0, 0);
    // LN2
    ln_kernel<<<MS, 256>>>(x, h, cD, cD, W.ln2_w + l * cD, W.ln2_b + l * cD);
    // fc1 + GELU
    launch_gemm(h, W.fc1_w + (long long)l * cD * cMLP, mlp,
                MS, cMLP, cD, cD, cMLP, cMLP,
                1, 1, 0, 0, 0, 0, 0, 0,
                W.fc1_b + (long long)l * cMLP, nullptr, 1.f, 0, 1);
    // fc2 + residual
    launch_gemm(mlp, W.fc2_w + (long long)l * cMLP * cD, x,
                MS, cD, cMLP, cMLP, cD, cD,
                1, 1, 0, 0, 0, 0, 0, 0,
                W.fc2_b + l * cD, x, 1.f, 0, 0);
}

extern "C" void kernel_launch(void* const* d_in, const int* in_sizes, int n_in,
                              void* d_out, int out_size)
{
    const float* in_img   = (const float*)d_in[0];
    const float* patch_w  = (const float*)d_in[1];
    const float* patch_b  = (const float*)d_in[2];
    const float* cls_tok  = (const float*)d_in[3];
    const float* pos      = (const float*)d_in[4];
    Weights W;
    W.ln1_w  = (const float*)d_in[5];
    W.ln1_b  = (const float*)d_in[6];
    W.qkv_w  = (const float*)d_in[7];
    W.qkv_b  = (const float*)d_in[8];
    W.proj_w = (const float*)d_in[9];
    W.proj_b = (const float*)d_in[10];
    W.ln2_w  = (const float*)d_in[11];
    W.ln2_b  = (const float*)d_in[12];
    W.fc1_w  = (const float*)d_in[13];
    W.fc1_b  = (const float*)d_in[14];
    W.fc2_w  = (const float*)d_in[15];
    W.fc2_b  = (const float*)d_in[16];
    const float* norm_w   = (const float*)d_in[17];
    const float* norm_b   = (const float*)d_in[18];
    const float* head_w   = (const float*)d_in[19];
    const float* head_b   = (const float*)d_in[20];
    const float* key_pool = (const float*)d_in[21];
    const float* freq     = (const float*)d_in[22];
    const float* prompts  = (const float*)d_in[23];
    const float* variance = (const float*)d_in[24];
    const float* inv_var  = (const float*)d_in[25];
    float* out = (float*)d_out;

    void* p;
    cudaGetSymbolAddress(&p, g_x);     float* x    = (float*)p;
    cudaGetSymbolAddress(&p, g_h);     float* h    = (float*)p;
    cudaGetSymbolAddress(&p, g_qkv);   float* qkv  = (float*)p;
    cudaGetSymbolAddress(&p, g_att);   float* att  = (float*)p;
    cudaGetSymbolAddress(&p, g_ao);    float* ao   = (float*)p;
    cudaGetSymbolAddress(&p, g_mlp);   float* mlp  = (float*)p;
    cudaGetSymbolAddress(&p, g_patch); float* pat  = (float*)p;
    cudaGetSymbolAddress(&p, g_cls);   float* clsq = (float*)p;
    cudaGetSymbolAddress(&p, g_feat);  float* feat = (float*)p;

    // ---- patchify + patch embed + cls/pos ----
    {
        int tot = cB * cNP * cD;
        patchify_kernel<<<(tot + 255) / 256, 256>>>(in_img);
        launch_gemm(pat, patch_w, ao, cB * cNP, cD, cD, cD, cD, cD,
                    1, 1, 0, 0, 0, 0, 0, 0, patch_b, nullptr, 1.f, 0, 0);
        int tot2 = cB * cS1 * cD;
        embed_kernel<<<(tot2 + 255) / 256, 256>>>(cls_tok, pos);
        copy_x0_kernel<<<(tot2 + 255) / 256, 256>>>();
    }

    // ---- pass 1 (S = 197) ----
    for (int l = 0; l < cL; l++)
        vit_layer(cS1, l, x, h, qkv, att, ao, mlp, W);

    // CLS query = LN(x)[:, 0]
    ln_kernel<<<cB, 256>>>(x, clsq, (long long)cS1 * cD, cD, norm_w, norm_b);

    // ---- routing ----
    fro_kernel<<<cPOOL, 256>>>(variance);
    routc_kernel<<<1, 32>>>(freq);
    score_kernel<<<dim3(cPOOL, cB), 256>>>(key_pool, inv_var);
    topk_kernel<<<1, 32>>>();
    {
        int tot = cB * cS2 * cD;
        buildsx_kernel<<<(tot + 255) / 256, 256>>>(prompts, pos);
    }

    // ---- pass 2 (S = 222) ----
    for (int l = 0; l < cL; l++)
        vit_layer(cS2, l, x, h, qkv, att, ao, mlp, W);

    // final LN, prompt-token mean, head
    ln_kernel<<<cB * cS2, 256>>>(x, h, cD, cD, norm_w, norm_b);
    featmean_kernel<<<cB, 256>>>();
    launch_gemm(feat, head_w, out, cB, cNCLS, cD, cD, cNCLS, cNCLS,
                1, 1, 0, 0, 0, 0, 0, 0, head_b, nullptr, 1.f, 0, 0);
}

// round 4
// speedup vs baseline: 2.6929x; 2.6929x over previous
#include <cuda_runtime.h>
#include <cuda_bf16.h>
#include <math.h>
#include <stdint.h>

// ---------------- problem constants ----------------
constexpr int cB = 32, cC = 3, cIMG = 224, cPS = 16, cG = 14, cNP = 196;
constexpr int cD = 768, cH = 12, cHD = 64, cL = 12, cMLP = 3072;
constexpr int cPOOL = 10, cSEL = 5, cPLEN = 5, cNCLS = 100;
constexpr int cS1 = 197, cS2 = 222;

// ---------------- scratch (device globals; no allocation allowed) ----------------
__device__ float g_x0 [cB*cS1*cD];
__device__ float g_x  [cB*cS2*cD];
__device__ float g_h  [cB*cS2*cD];
__device__ float g_qkv[cB*cS2*3*cD];
__device__ float g_att[cB*cH*cS2*cS2];
__device__ float g_ao [cB*cS2*cD];
__device__ float g_mlp[cB*cS2*cMLP];
__device__ float g_patch[cB*cNP*cD];
__device__ float g_cls[cB*cD];
__device__ float g_fro[cPOOL];
__device__ float g_routc[cPOOL];
__device__ float g_score[cB*cPOOL];
__device__ int   g_topk[cB*cSEL];
__device__ float g_feat[cB*cD];

// bf16 hi/lo weight copies, stored TRANSPOSED as [N, K] per layer
__device__ __nv_bfloat16 g_wq_h[cL*3*cD*cD], g_wq_l[cL*3*cD*cD];
__device__ __nv_bfloat16 g_wp_h[cL*cD*cD],   g_wp_l[cL*cD*cD];
__device__ __nv_bfloat16 g_w1_h[cL*cMLP*cD], g_w1_l[cL*cMLP*cD];
__device__ __nv_bfloat16 g_w2_h[cL*cD*cMLP], g_w2_l[cL*cD*cMLP];
__device__ __nv_bfloat16 g_wpat_h[cD*cD],    g_wpat_l[cD*cD];
// bf16 hi/lo activation scratch (A operand)
__device__ __nv_bfloat16 g_ah[cB*cS2*cMLP], g_al[cB*cS2*cMLP];

// ---------------- PTX helpers (compute_80-compatible only) ----------------
__device__ __forceinline__ uint32_t smem_u32(const void* p) {
    uint32_t a;
    asm("{ .reg .u64 t; cvta.to.shared.u64 t, %1; cvt.u32.u64 %0, t; }" : "=r"(a) : "l"(p));
    return a;
}
#define CP_ASYNC16(sa, g) \
    asm volatile("cp.async.cg.shared.global [%0], [%1], 16;" :: "r"(sa), "l"(g))
#define CP_COMMIT() asm volatile("cp.async.commit_group;" ::: "memory")
#define CP_WAIT(n)  asm volatile("cp.async.wait_group %0;" :: "n"(n) : "memory")

__device__ __forceinline__ void ldsm4(uint32_t* r, uint32_t addr) {
    asm volatile("ldmatrix.sync.aligned.m8n8.x4.shared.b16 {%0,%1,%2,%3}, [%4];"
        : "=r"(r[0]), "=r"(r[1]), "=r"(r[2]), "=r"(r[3]) : "r"(addr));
}
__device__ __forceinline__ void mma16816(float* d, const uint32_t* a, const uint32_t* b) {
    asm volatile(
        "mma.sync.aligned.m16n8k16.row.col.f32.bf16.bf16.f32 "
        "{%0,%1,%2,%3}, {%4,%5,%6,%7}, {%8,%9}, {%0,%1,%2,%3};"
        : "+f"(d[0]), "+f"(d[1]), "+f"(d[2]), "+f"(d[3])
        : "r"(a[0]), "r"(a[1]), "r"(a[2]), "r"(a[3]), "r"(b[0]), "r"(b[1]));
}

// smem tile: 128 rows x 32 bf16, row stride 80 B (64 data + 16 pad -> conflict-free)
constexpr int T_ROWB  = 80;
constexpr int T_BYTES = 128 * T_ROWB;          // 10240
constexpr int STAGE_B = 4 * T_BYTES;           // Ah, Al, Bh, Bl
constexpr int MM_SMEM = 2 * STAGE_B;           // 81920

// ---------------- bf16x3 tensor-core GEMM: C[M,N] = A[M,K] @ B[N,K]^T ----------------
__global__ __launch_bounds__(256, 1) void mm_gemm(
    const __nv_bfloat16* __restrict__ Ah, const __nv_bfloat16* __restrict__ Al,
    const __nv_bfloat16* __restrict__ Bh, const __nv_bfloat16* __restrict__ Bl,
    float* __restrict__ C, int M, int N, int K,
    const float* __restrict__ bias, const float* __restrict__ Res, int act)
{
    extern __shared__ char sm[];
    const uint32_t smb = smem_u32(sm);
    int t = threadIdx.x, warp = t >> 5, lane = t & 31;
    int row0 = blockIdx.y * 128, col0 = blockIdx.x * 128;
    int wm = warp & 1, wn = warp >> 1;         // warp tile: rows wm*64, cols wn*32

    const __nv_bfloat16* srcs[4] = {Ah, Al, Bh, Bl};
    int bases[4] = {row0, row0, col0, col0};
    int maxr [4] = {M - 1, M - 1, N - 1, N - 1};

    float acc[4][4][4];
    #pragma unroll
    for (int i = 0; i < 4; i++)
        #pragma unroll
        for (int j = 0; j < 4; j++)
            #pragma unroll
            for (int r = 0; r < 4; r++) acc[i][j][r] = 0.f;

    int nk = K >> 5;

    // stage loader: 2048 x 16B segments, 8 per thread
    auto load_stage = [&](int s, int c) {
        int k0 = c << 5;
        uint32_t sb = smb + (uint32_t)s * STAGE_B;
        #pragma unroll
        for (int i = 0; i < 8; i++) {
            int sid  = t + 256 * i;
            int tile = sid >> 9;
            int e    = sid & 511;
            int row  = e >> 2, sg = e & 3;
            int gr = bases[tile] + row;
            if (gr > maxr[tile]) gr = maxr[tile];
            const __nv_bfloat16* g = srcs[tile] + (size_t)gr * K + k0 + sg * 8;
            uint32_t sa = sb + (uint32_t)tile * T_BYTES + (uint32_t)(row * T_ROWB + sg * 16);
            CP_ASYNC16(sa, g);
        }
        CP_COMMIT();
    };

    load_stage(0, 0);

    int g2 = lane >> 3, lr = lane & 7;

    for (int c = 0; c < nk; c++) {
        if (c + 1 < nk) load_stage((c + 1) & 1, c + 1);
        if (c + 1 < nk) { CP_WAIT(1); } else { CP_WAIT(0); }
        __syncthreads();

        uint32_t tb = smb + (uint32_t)(c & 1) * STAGE_B;
        #pragma unroll
        for (int ks = 0; ks < 2; ks++) {
            // A fragments: group0 row+0 seg s0, group1 row+8 seg s0, group2 row+0 seg s0+1, group3 row+8 seg s0+1
            int a_row_add = (g2 & 1) ? 8 : 0;
            int a_seg     = ks * 2 + (g2 >> 1);
            uint32_t afh[4][4], afl[4][4];
            #pragma unroll
            for (int mt = 0; mt < 4; mt++) {
                int r = wm * 64 + mt * 16 + a_row_add + lr;
                uint32_t ad = tb + (uint32_t)(r * T_ROWB + a_seg * 16);
                ldsm4(afh[mt], ad);
                ldsm4(afl[mt], ad + T_BYTES);
            }
            // B fragments: group0 row+0 seg s0, group1 row+0 seg s0+1, group2 row+8 seg s0, group3 row+8 seg s0+1
            int b_row_add = (g2 >> 1) ? 8 : 0;
            int b_seg     = ks * 2 + (g2 & 1);
            uint32_t bfh[4][2], bfl[4][2];
            #pragma unroll
            for (int np = 0; np < 2; np++) {
                int r = wn * 32 + np * 16 + b_row_add + lr;
                uint32_t bd = tb + 2u * T_BYTES + (uint32_t)(r * T_ROWB + b_seg * 16);
                uint32_t q[4];
                ldsm4(q, bd);
                bfh[np*2][0] = q[0]; bfh[np*2][1] = q[1];
                bfh[np*2+1][0] = q[2]; bfh[np*2+1][1] = q[3];
                ldsm4(q, bd + T_BYTES);
                bfl[np*2][0] = q[0]; bfl[np*2][1] = q[1];
                bfl[np*2+1][0] = q[2]; bfl[np*2+1][1] = q[3];
            }
            #pragma unroll
            for (int mt = 0; mt < 4; mt++)
                #pragma unroll
                for (int nt = 0; nt < 4; nt++)
                    mma16816(acc[mt][nt], afh[mt], bfh[nt]);
            #pragma unroll
            for (int mt = 0; mt < 4; mt++)
                #pragma unroll
                for (int nt = 0; nt < 4; nt++)
                    mma16816(acc[mt][nt], afh[mt], bfl[nt]);
            #pragma unroll
            for (int mt = 0; mt < 4; mt++)
                #pragma unroll
                for (int nt = 0; nt < 4; nt++)
                    mma16816(acc[mt][nt], afl[mt], bfh[nt]);
        }
        __syncthreads();
    }

    // ---- epilogue ----
    int qr = lane >> 2, qc = lane & 3;
    #pragma unroll
    for (int mt = 0; mt < 4; mt++) {
        #pragma unroll
        for (int half = 0; half < 2; half++) {
            int gr = row0 + wm * 64 + mt * 16 + half * 8 + qr;
            if (gr >= M) continue;
            float* crow = C + (size_t)gr * N;
            const float* rrow = Res ? Res + (size_t)gr * N : (const float*)0;
            #pragma unroll
            for (int nt = 0; nt < 4; nt++) {
                int gc = col0 + wn * 32 + nt * 8 + qc * 2;
                float v0 = acc[mt][nt][half * 2 + 0] + bias[gc];
                float v1 = acc[mt][nt][half * 2 + 1] + bias[gc + 1];
                if (rrow) { v0 += rrow[gc]; v1 += rrow[gc + 1]; }
                if (act) {
                    v0 = 0.5f * v0 * (1.f + erff(v0 * 0.70710678118654752f));
                    v1 = 0.5f * v1 * (1.f + erff(v1 * 0.70710678118654752f));
                }
                crow[gc]     = v0;
                crow[gc + 1] = v1;
            }
        }
    }
}

// ---------------- fp32 -> bf16 hi/lo split ----------------
__global__ void cvt_split_kernel(const float* __restrict__ x,
                                 __nv_bfloat16* __restrict__ h,
                                 __nv_bfloat16* __restrict__ l, int n)
{
    int stride = gridDim.x * blockDim.x;
    for (int i = blockIdx.x * blockDim.x + threadIdx.x; i < n; i += stride) {
        float v = x[i];
        __nv_bfloat16 hi = __float2bfloat16(v);
        h[i] = hi;
        l[i] = __float2bfloat16(v - __bfloat162float(hi));
    }
}

// transpose + split: src fp32 [K,N] (grid.z layers) -> dst bf16 [N,K]
__global__ void wsplit_t_kernel(const float* __restrict__ src,
                                __nv_bfloat16* __restrict__ dh,
                                __nv_bfloat16* __restrict__ dl, int K, int N)
{
    __shared__ float tile[32][33];
    size_t lo = (size_t)blockIdx.z * K * N;
    const float* s = src + lo;
    __nv_bfloat16* oh = dh + lo;
    __nv_bfloat16* ol = dl + lo;
    int k0 = blockIdx.y * 32, n0 = blockIdx.x * 32;
    int tx = threadIdx.x, ty = threadIdx.y;
    #pragma unroll
    for (int i = 0; i < 4; i++) {
        int r = ty + i * 8;
        tile[r][tx] = s[(size_t)(k0 + r) * N + n0 + tx];
    }
    __syncthreads();
    #pragma unroll
    for (int i = 0; i < 4; i++) {
        int r = ty + i * 8;
        float v = tile[tx][r];
        __nv_bfloat16 hi = __float2bfloat16(v);
        size_t o = (size_t)(n0 + r) * K + k0 + tx;
        oh[o] = hi;
        ol[o] = __float2bfloat16(v - __bfloat162float(hi));
    }
}

// ---------------- reductions (blockDim == 256) ----------------
__device__ __forceinline__ float block_sum(float v, float* red) {
    int t = threadIdx.x;
    #pragma unroll
    for (int o = 16; o > 0; o >>= 1) v += __shfl_xor_sync(0xffffffffu, v, o);
    if ((t & 31) == 0) red[t >> 5] = v;
    __syncthreads();
    if (t == 0) {
        float s = 0.f;
        #pragma unroll
        for (int i = 0; i < 8; i++) s += red[i];
        red[0] = s;
    }
    __syncthreads();
    float r = red[0];
    __syncthreads();
    return r;
}
__device__ __forceinline__ float block_max(float v, float* red) {
    int t = threadIdx.x;
    #pragma unroll
    for (int o = 16; o > 0; o >>= 1) v = fmaxf(v, __shfl_xor_sync(0xffffffffu, v, o));
    if ((t & 31) == 0) red[t >> 5] = v;
    __syncthreads();
    if (t == 0) {
        float m = red[0];
        #pragma unroll
        for (int i = 1; i < 8; i++) m = fmaxf(m, red[i]);
        red[0] = m;
    }
    __syncthreads();
    float r = red[0];
    __syncthreads();
    return r;
}

// ---------------- fp32 batched GEMM (attention + head) ----------------
__global__ __launch_bounds__(256) void gemm_kernel(
    const float* __restrict__ A, const float* __restrict__ Bm, float* __restrict__ C,
    int M, int N, int K, int lda, int ldb, int ldc,
    int HB,
    long long sAb, long long sAh, long long sBb, long long sBh,
    long long sCb, long long sCh,
    const float* __restrict__ bias, const float* __restrict__ Res,
    float alpha, int transB, int act)
{
    __shared__ float As[16][68];
    __shared__ float Bs[16][68];
    int t  = threadIdx.x;
    int bz = blockIdx.z;
    int bb = bz / HB, hh = bz - bb * HB;
    const float* Ab = A  + bb * sAb + hh * sAh;
    const float* Bb = Bm + bb * sBb + hh * sBh;
    float*       Cb = C  + bb * sCb + hh * sCh;
    const float* Rb = Res ? Res + bb * sCb + hh * sCh : (const float*)0;
    int row0 = blockIdx.y * 64, col0 = blockIdx.x * 64;
    int tx = t & 15, ty = t >> 4;
    float acc[4][4];
    #pragma unroll
    for (int i = 0; i < 4; i++)
        #pragma unroll
        for (int j = 0; j < 4; j++) acc[i][j] = 0.f;

    for (int k0 = 0; k0 < K; k0 += 16) {
        #pragma unroll
        for (int s = 0; s < 4; s++) {
            int e = t * 4 + s;
            int m = e >> 4, kk = e & 15;
            int gr = row0 + m, gk = k0 + kk;
            As[kk][m] = (gr < M && gk < K) ? Ab[(long long)gr * lda + gk] : 0.f;
        }
        if (transB) {
            #pragma unroll
            for (int s = 0; s < 4; s++) {
                int e = t * 4 + s;
                int n = e >> 4, kk = e & 15;
                int gn = col0 + n, gk = k0 + kk;
                Bs[kk][n] = (gn < N && gk < K) ? Bb[(long long)gn * ldb + gk] : 0.f;
            }
        } else {
            #pragma unroll
            for (int s = 0; s < 4; s++) {
                int e = t + 256 * s;
                int kk = e >> 6, n = e & 63;
                int gn = col0 + n, gk = k0 + kk;
                Bs[kk][n] = (gn < N && gk < K) ? Bb[(long long)gk * ldb + gn] : 0.f;
            }
        }
        __syncthreads();
        #pragma unroll
        for (int kk = 0; kk < 16; kk++) {
            float4 a4 = *(const float4*)&As[kk][ty * 4];
            float4 b4 = *(const float4*)&Bs[kk][tx * 4];
            float ar[4] = {a4.x, a4.y, a4.z, a4.w};
            float br[4] = {b4.x, b4.y, b4.z, b4.w};
            #pragma unroll
            for (int i = 0; i < 4; i++)
                #pragma unroll
                for (int j = 0; j < 4; j++)
                    acc[i][j] = fmaf(ar[i], br[j], acc[i][j]);
        }
        __syncthreads();
    }

    #pragma unroll
    for (int i = 0; i < 4; i++) {
        int gr = row0 + ty * 4 + i;
        if (gr >= M) continue;
        #pragma unroll
        for (int j = 0; j < 4; j++) {
            int gc = col0 + tx * 4 + j;
            if (gc >= N) continue;
            float v = alpha * acc[i][j];
            if (bias) v += bias[gc];
            if (Rb)   v += Rb[(long long)gr * ldc + gc];
            if (act)  v = 0.5f * v * (1.f + erff(v * 0.70710678118654752f));
            Cb[(long long)gr * ldc + gc] = v;
        }
    }
}

// ---------------- LayerNorm ----------------
__global__ __launch_bounds__(256) void ln_kernel(
    const float* __restrict__ X, float* __restrict__ Y,
    long long istride, long long ostride,
    const float* __restrict__ w, const float* __restrict__ b)
{
    __shared__ float red[8];
    long long r = blockIdx.x;
    const float* x = X + r * istride;
    float*       y = Y + r * ostride;
    int t = threadIdx.x;
    float v[3];
    #pragma unroll
    for (int i = 0; i < 3; i++) v[i] = x[t + 256 * i];
    float mean = block_sum(v[0] + v[1] + v[2], red) * (1.f / 768.f);
    float d0 = v[0] - mean, d1 = v[1] - mean, d2 = v[2] - mean;
    float var = block_sum(d0*d0 + d1*d1 + d2*d2, red) * (1.f / 768.f);
    float rstd = rsqrtf(var + 1e-6f);
    #pragma unroll
    for (int i = 0; i < 3; i++) {
        int c = t + 256 * i;
        y[c] = (v[i] - mean) * rstd * w[c] + b[c];
    }
}

// ---------------- softmax ----------------
__global__ __launch_bounds__(256) void softmax_kernel(float* __restrict__ X, int n)
{
    __shared__ float red[8];
    long long r = blockIdx.x;
    float* x = X + r * (long long)n;
    int t = threadIdx.x;
    float v = (t < n) ? x[t] : -3.4e38f;
    float mx = block_max(v, red);
    float e = (t < n) ? expf(v - mx) : 0.f;
    float s = block_sum(e, red);
    if (t < n) x[t] = e / s;
}

// ---------------- patchify / embed / misc ----------------
__global__ void patchify_kernel(const float* __restrict__ in)
{
    int total = cB * cNP * cD;
    for (int idx = blockIdx.x * blockDim.x + threadIdx.x; idx < total;
         idx += gridDim.x * blockDim.x) {
        int d  = idx % cD;
        int rp = idx / cD;
        int p  = rp % cNP;
        int b  = rp / cNP;
        int c  = d >> 8;
        int ph = (d >> 4) & 15;
        int pw = d & 15;
        int gy = p / cG, gx = p % cG;
        g_patch[idx] = in[((long long)(b * cC + c) * cIMG + gy * cPS + ph) * cIMG
                          + gx * cPS + pw];
    }
}

__global__ void embed_kernel(const float* __restrict__ cls, const float* __restrict__ pos)
{
    int total = cB * cS1 * cD;
    for (int idx = blockIdx.x * blockDim.x + threadIdx.x; idx < total;
         idx += gridDim.x * blockDim.x) {
        int d  = idx % cD;
        int rs = idx / cD;
        int s  = rs % cS1;
        int b  = rs / cS1;
        float v = (s == 0) ? cls[d] : g_ao[((long long)b * cNP + (s - 1)) * cD + d];
        g_x0[idx] = v + pos[s * cD + d];
    }
}

__global__ void copy_x0_kernel()
{
    int total = cB * cS1 * cD;
    for (int idx = blockIdx.x * blockDim.x + threadIdx.x; idx < total;
         idx += gridDim.x * blockDim.x)
        g_x[idx] = g_x0[idx];
}

__global__ __launch_bounds__(256) void fro_kernel(const float* __restrict__ var)
{
    __shared__ float red[8];
    int p = blockIdx.x;
    const float* vp = var + (long long)p * cD * cD;
    float s = 0.f;
    for (int i = threadIdx.x; i < cD * cD; i += 256) { float v = vp[i]; s += v * v; }
    s = block_sum(s, red);
    if (threadIdx.x == 0) g_fro[p] = s;
}

__global__ void routc_kernel(const float* __restrict__ freq)
{
    if (threadIdx.x == 0 && blockIdx.x == 0) {
        float mx = freq[0];
        for (int p = 1; p < cPOOL; p++) mx = fmaxf(mx, freq[p]);
        float w[cPOOL]; float nsq = 0.f;
        for (int p = 0; p < cPOOL; p++) { w[p] = mx - freq[p]; nsq += w[p] * w[p]; }
        float nrm = fmaxf(sqrtf(nsq), 1e-12f);
        for (int p = 0; p < cPOOL; p++) {
            float wn = w[p] / nrm;
            g_routc[p] = 0.25f * logf(g_fro[p]) + logf(fmaxf(wn, 1e-30f));
        }
    }
}

__global__ __launch_bounds__(256) void score_kernel(const float* __restrict__ keypool,
                                                    const float* __restrict__ ivar)
{
    __shared__ float diff[cD];
    __shared__ float red[8];
    int p = blockIdx.x, b = blockIdx.y;
    for (int d = threadIdx.x; d < cD; d += 256)
        diff[d] = g_cls[b * cD + d] - keypool[p * cD + d];
    __syncthreads();
    const float* iv = ivar + (long long)p * cD * cD;
    float acc = 0.f;
    for (int idx = threadIdx.x; idx < cD * cD; idx += 256) {
        int d = idx / cD, e = idx - d * cD;
        acc += diff[d] * iv[idx] * diff[e];
    }
    float q = block_sum(acc, red);
    if (threadIdx.x == 0) g_score[b * cPOOL + p] = -0.5f * q + g_routc[p];
}

__global__ void topk_kernel()
{
    int b = threadIdx.x;
    if (b < cB) {
        float s[cPOOL]; bool used[cPOOL];
        for (int p = 0; p < cPOOL; p++) { s[p] = g_score[b * cPOOL + p]; used[p] = false; }
        for (int k = 0; k < cSEL; k++) {
            int best = 0; float bv = 3.4e38f; bool have = false;
            for (int p = 0; p < cPOOL; p++)
                if (!used[p] && (!have || s[p] < bv)) { bv = s[p]; best = p; have = true; }
            used[best] = true;
            g_topk[b * cSEL + k] = best;
        }
    }
}

__global__ void buildsx_kernel(const float* __restrict__ prompts, const float* __restrict__ pos)
{
    int total = cB * cS2 * cD;
    for (int idx = blockIdx.x * blockDim.x + threadIdx.x; idx < total;
         idx += gridDim.x * blockDim.x) {
        int d  = idx % cD;
        int rs = idx / cD;
        int s  = rs % cS2;
        int b  = rs / cS2;
        float v;
        if (s == 0) {
            v = g_x0[(long long)b * cS1 * cD + d];
        } else if (s <= cSEL * cPLEN) {
            int k = (s - 1) / cPLEN, j = (s - 1) % cPLEN;
            int pr = g_topk[b * cSEL + k];
            v = prompts[((long long)pr * cPLEN + j) * cD + d] + pos[d];
        } else {
            v = g_x0[((long long)b * cS1 + (s - cSEL * cPLEN)) * cD + d];
        }
        g_x[idx] = v;
    }
}

__global__ __launch_bounds__(256) void featmean_kernel()
{
    int b = blockIdx.x;
    for (int d = threadIdx.x; d < cD; d += 256) {
        float s = 0.f;
        for (int t2 = 1; t2 <= cSEL * cPLEN; t2++)
            s += g_h[((long long)b * cS2 + t2) * cD + d];
        g_feat[b * cD + d] = s * (1.f / 25.f);
    }
}

// ---------------- host orchestration ----------------
static void launch_gemm(const float* A, const float* Bm, float* C,
                        int M, int N, int K, int lda, int ldb, int ldc,
                        int nb, int HB,
                        long long sAb, long long sAh, long long sBb, long long sBh,
                        long long sCb, long long sCh,
                        const float* bias, const float* Res,
                        float alpha, int transB, int act)
{
    dim3 grid((N + 63) / 64, (M + 63) / 64, nb);
    gemm_kernel<<<grid, 256>>>(A, Bm, C, M, N, K, lda, ldb, ldc, HB,
                               sAb, sAh, sBb, sBh, sCb, sCh, bias, Res,
                               alpha, transB, act);
}

struct Weights {
    const float *ln1_w, *ln1_b, *qkv_b, *proj_b, *ln2_w, *ln2_b, *fc1_b, *fc2_b;
};

struct BfPtrs {
    __nv_bfloat16 *wq_h, *wq_l, *wp_h, *wp_l, *w1_h, *w1_l, *w2_h, *w2_l, *wpat_h, *wpat_l;
    __nv_bfloat16 *ah, *al;
};

static void launch_tc(const __nv_bfloat16* ah, const __nv_bfloat16* al,
                      const __nv_bfloat16* bh, const __nv_bfloat16* bl,
                      float* C, int M, int N, int K,
                      const float* bias, const float* Res, int act)
{
    dim3 grid(N / 128, (M + 127) / 128);
    mm_gemm<<<grid, 256, MM_SMEM>>>(ah, al, bh, bl, C, M, N, K, bias, Res, act);
}

static void cvt(const float* x, __nv_bfloat16* h, __nv_bfloat16* l, int n)
{
    cvt_split_kernel<<<2048, 256>>>(x, h, l, n);
}

static void vit_layer(int S, int l, float* x, float* h, float* qkv, float* att,
                      float* ao, float* mlp, const Weights& W, const BfPtrs& P)
{
    int MS = cB * S;
    ln_kernel<<<MS, 256>>>(x, h, cD, cD, W.ln1_w + l * cD, W.ln1_b + l * cD);
    cvt(h, P.ah, P.al, MS * cD);
    launch_tc(P.ah, P.al, P.wq_h + (size_t)l * 3 * cD * cD, P.wq_l + (size_t)l * 3 * cD * cD,
              qkv, MS, 3 * cD, cD, W.qkv_b + (size_t)l * 3 * cD, nullptr, 0);
    launch_gemm(qkv, qkv + cD, att,
                S, S, cHD, 3 * cD, 3 * cD, S,
                cB * cH, cH,
                (long long)S * 3 * cD, cHD,
                (long long)S * 3 * cD, cHD,
                (long long)cH * S * S, (long long)S * S,
                nullptr, nullptr, 0.125f, 1, 0);
    softmax_kernel<<<cB * cH * S, 256>>>(att, S);
    launch_gemm(att, qkv + 2 * cD, ao,
                S, cHD, S, S, 3 * cD, cD,
                cB * cH, cH,
                (long long)cH * S * S, (long long)S * S,
                (long long)S * 3 * cD, cHD,
                (long long)S * cD, cHD,
                nullptr, nullptr, 1.f, 0, 0);
    cvt(ao, P.ah, P.al, MS * cD);
    launch_tc(P.ah, P.al, P.wp_h + (size_t)l * cD * cD, P.wp_l + (size_t)l * cD * cD,
              x, MS, cD, cD, W.proj_b + l * cD, x, 0);
    ln_kernel<<<MS, 256>>>(x, h, cD, cD, W.ln2_w + l * cD, W.ln2_b + l * cD);
    cvt(h, P.ah, P.al, MS * cD);
    launch_tc(P.ah, P.al, P.w1_h + (size_t)l * cMLP * cD, P.w1_l + (size_t)l * cMLP * cD,
              mlp, MS, cMLP, cD, W.fc1_b + (size_t)l * cMLP, nullptr, 1);
    cvt(mlp, P.ah, P.al, MS * cMLP);
    launch_tc(P.ah, P.al, P.w2_h + (size_t)l * cD * cMLP, P.w2_l + (size_t)l * cD * cMLP,
              x, MS, cD, cMLP, W.fc2_b + l * cD, x, 0);
}

extern "C" void kernel_launch(void* const* d_in, const int* in_sizes, int n_in,
                              void* d_out, int out_size)
{
    const float* in_img   = (const float*)d_in[0];
    const float* patch_w  = (const float*)d_in[1];
    const float* patch_b  = (const float*)d_in[2];
    const float* cls_tok  = (const float*)d_in[3];
    const float* pos      = (const float*)d_in[4];
    const float* ln1_w    = (const float*)d_in[5];
    const float* ln1_b    = (const float*)d_in[6];
    const float* qkv_w    = (const float*)d_in[7];
    const float* qkv_b    = (const float*)d_in[8];
    const float* proj_w   = (const float*)d_in[9];
    const float* proj_b   = (const float*)d_in[10];
    const float* ln2_w    = (const float*)d_in[11];
    const float* ln2_b    = (const float*)d_in[12];
    const float* fc1_w    = (const float*)d_in[13];
    const float* fc1_b    = (const float*)d_in[14];
    const float* fc2_w    = (const float*)d_in[15];
    const float* fc2_b    = (const float*)d_in[16];
    const float* norm_w   = (const float*)d_in[17];
    const float* norm_b   = (const float*)d_in[18];
    const float* head_w   = (const float*)d_in[19];
    const float* head_b   = (const float*)d_in[20];
    const float* key_pool = (const float*)d_in[21];
    const float* freq     = (const float*)d_in[22];
    const float* prompts  = (const float*)d_in[23];
    const float* variance = (const float*)d_in[24];
    const float* inv_var  = (const float*)d_in[25];
    float* out = (float*)d_out;

    Weights W;
    W.ln1_w = ln1_w; W.ln1_b = ln1_b; W.qkv_b = qkv_b; W.proj_b = proj_b;
    W.ln2_w = ln2_w; W.ln2_b = ln2_b; W.fc1_b = fc1_b; W.fc2_b = fc2_b;

    void* p;
    cudaGetSymbolAddress(&p, g_x);     float* x    = (float*)p;
    cudaGetSymbolAddress(&p, g_h);     float* h    = (float*)p;
    cudaGetSymbolAddress(&p, g_qkv);   float* qkv  = (float*)p;
    cudaGetSymbolAddress(&p, g_att);   float* att  = (float*)p;
    cudaGetSymbolAddress(&p, g_ao);    float* ao   = (float*)p;
    cudaGetSymbolAddress(&p, g_mlp);   float* mlp  = (float*)p;
    cudaGetSymbolAddress(&p, g_patch); float* pat  = (float*)p;
    cudaGetSymbolAddress(&p, g_cls);   float* clsq = (float*)p;
    cudaGetSymbolAddress(&p, g_feat);  float* feat = (float*)p;

    BfPtrs P;
    cudaGetSymbolAddress(&p, g_wq_h);   P.wq_h   = (__nv_bfloat16*)p;
    cudaGetSymbolAddress(&p, g_wq_l);   P.wq_l   = (__nv_bfloat16*)p;
    cudaGetSymbolAddress(&p, g_wp_h);   P.wp_h   = (__nv_bfloat16*)p;
    cudaGetSymbolAddress(&p, g_wp_l);   P.wp_l   = (__nv_bfloat16*)p;
    cudaGetSymbolAddress(&p, g_w1_h);   P.w1_h   = (__nv_bfloat16*)p;
    cudaGetSymbolAddress(&p, g_w1_l);   P.w1_l   = (__nv_bfloat16*)p;
    cudaGetSymbolAddress(&p, g_w2_h);   P.w2_h   = (__nv_bfloat16*)p;
    cudaGetSymbolAddress(&p, g_w2_l);   P.w2_l   = (__nv_bfloat16*)p;
    cudaGetSymbolAddress(&p, g_wpat_h); P.wpat_h = (__nv_bfloat16*)p;
    cudaGetSymbolAddress(&p, g_wpat_l); P.wpat_l = (__nv_bfloat16*)p;
    cudaGetSymbolAddress(&p, g_ah);     P.ah     = (__nv_bfloat16*)p;
    cudaGetSymbolAddress(&p, g_al);     P.al     = (__nv_bfloat16*)p;

    cudaFuncSetAttribute(mm_gemm, cudaFuncAttributeMaxDynamicSharedMemorySize, MM_SMEM);

    // ---- weight conversion (transpose + hi/lo split) ----
    {
        dim3 blk(32, 8);
        wsplit_t_kernel<<<dim3(3 * cD / 32, cD / 32, cL), blk>>>(qkv_w, P.wq_h, P.wq_l, cD, 3 * cD);
        wsplit_t_kernel<<<dim3(cD / 32, cD / 32, cL), blk>>>(proj_w, P.wp_h, P.wp_l, cD, cD);
        wsplit_t_kernel<<<dim3(cMLP / 32, cD / 32, cL), blk>>>(fc1_w, P.w1_h, P.w1_l, cD, cMLP);
        wsplit_t_kernel<<<dim3(cD / 32, cMLP / 32, cL), blk>>>(fc2_w, P.w2_h, P.w2_l, cMLP, cD);
        wsplit_t_kernel<<<dim3(cD / 32, cD / 32, 1), blk>>>(patch_w, P.wpat_h, P.wpat_l, cD, cD);
    }

    // ---- patchify + patch embed + cls/pos ----
    {
        int tot = cB * cNP * cD;
        patchify_kernel<<<(tot + 255) / 256, 256>>>(in_img);
        cvt(pat, P.ah, P.al, tot);
        launch_tc(P.ah, P.al, P.wpat_h, P.wpat_l, ao, cB * cNP, cD, cD, patch_b, nullptr, 0);
        int tot2 = cB * cS1 * cD;
        embed_kernel<<<(tot2 + 255) / 256, 256>>>(cls_tok, pos);
        copy_x0_kernel<<<(tot2 + 255) / 256, 256>>>();
    }

    // ---- pass 1 (S = 197) ----
    for (int l = 0; l < cL; l++)
        vit_layer(cS1, l, x, h, qkv, att, ao, mlp, W, P);

    ln_kernel<<<cB, 256>>>(x, clsq, (long long)cS1 * cD, cD, norm_w, norm_b);

    // ---- routing ----
    fro_kernel<<<cPOOL, 256>>>(variance);
    routc_kernel<<<1, 32>>>(freq);
    score_kernel<<<dim3(cPOOL, cB), 256>>>(key_pool, inv_var);
    topk_kernel<<<1, 32>>>();
    {
        int tot = cB * cS2 * cD;
        buildsx_kernel<<<(tot + 255) / 256, 256>>>(prompts, pos);
    }

    // ---- pass 2 (S = 222) ----
    for (int l = 0; l < cL; l++)
        vit_layer(cS2, l, x, h, qkv, att, ao, mlp, W, P);

    ln_kernel<<<cB * cS2, 256>>>(x, h, cD, cD, norm_w, norm_b);
    featmean_kernel<<<cB, 256>>>();
    launch_gemm(feat, head_w, out, cB, cNCLS, cD, cD, cNCLS, cNCLS,
                1, 1, 0, 0, 0, 0, 0, 0, head_b, nullptr, 1.f, 0, 0);
}